// round 1
// baseline (speedup 1.0000x reference)
#include <cuda_runtime.h>

// EM_fusion: softmax over [x, x] is exactly [0.5, 0.5], so the reference
// reduces to fused = 0.5*f1 + 0.5*f2. Pure HBM-bound streaming mean.
// B*D = 131072*768 = 100663296 floats per input (divisible by 4).

__global__ void em_fusion_mean_kernel(const float4* __restrict__ a,
                                      const float4* __restrict__ b,
                                      float4* __restrict__ out,
                                      int n4) {
    int i = blockIdx.x * blockDim.x + threadIdx.x;
    if (i < n4) {
        float4 va = __ldg(&a[i]);
        float4 vb = __ldg(&b[i]);
        float4 vo;
        vo.x = 0.5f * (va.x + vb.x);
        vo.y = 0.5f * (va.y + vb.y);
        vo.z = 0.5f * (va.z + vb.z);
        vo.w = 0.5f * (va.w + vb.w);
        // output is write-once, never re-read -> streaming store
        __stcs(&out[i], vo);
    }
}

// Tail kernel only needed if n % 4 != 0 (it isn't here, but keep it correct).
__global__ void em_fusion_tail_kernel(const float* __restrict__ a,
                                      const float* __restrict__ b,
                                      float* __restrict__ out,
                                      int start, int n) {
    int i = start + blockIdx.x * blockDim.x + threadIdx.x;
    if (i < n) {
        out[i] = 0.5f * (a[i] + b[i]);
    }
}

extern "C" void kernel_launch(void* const* d_in, const int* in_sizes, int n_in,
                              void* d_out, int out_size) {
    const float* f1 = (const float*)d_in[0];
    const float* f2 = (const float*)d_in[1];
    float* out = (float*)d_out;

    int n = in_sizes[0];          // 100663296 elements
    int n4 = n >> 2;              // float4 count
    int tail_start = n4 << 2;

    const int threads = 256;
    int blocks = (n4 + threads - 1) / threads;
    em_fusion_mean_kernel<<<blocks, threads>>>(
        (const float4*)f1, (const float4*)f2, (float4*)out, n4);

    int tail = n - tail_start;
    if (tail > 0) {
        em_fusion_tail_kernel<<<1, 128>>>(f1, f2, out, tail_start, n);
    }
}